// round 16
// baseline (speedup 1.0000x reference)
#include <cuda_runtime.h>
#include <cuda_fp16.h>
#include <cstdint>

#define TT 512
#define BD 2
#define TOK 256
#define TPR 12
#define HID 32
#define INNER 256
#define ATT_SCALE 0.0625f
#define BN_EPS 1e-5f

// ---------------- scratch (device globals: no allocation allowed) ----------
__device__ float g_w1f[TPR * HID];
__device__ float g_c1[HID];
__device__ float g_c2[TOK];
__device__ uint32_t g_w2h[TOK * 16];     // w2^T, BN-folded, f16 pairs [n][kpair]
__device__ float g_xb[BD * TT * TOK];
__device__ float g_qkv[BD * TT * 3 * INNER];
__device__ float g_dots[BD * TT * TT];

__device__ __forceinline__ uint32_t h2_bits(float a, float b) {
    __half2 h = __floats2half2_rn(a, b);
    return *reinterpret_cast<uint32_t*>(&h);
}

// mma.sync m16n8k16 f16 (baseline PTX, works on sm_103)
__device__ __forceinline__ void mmaH(float* d, const uint32_t* a, const uint32_t* b) {
    asm volatile(
        "mma.sync.aligned.m16n8k16.row.col.f32.f16.f16.f32 "
        "{%0,%1,%2,%3}, {%4,%5,%6,%7}, {%8,%9}, {%0,%1,%2,%3};"
        : "+f"(d[0]), "+f"(d[1]), "+f"(d[2]), "+f"(d[3])
        : "r"(a[0]), "r"(a[1]), "r"(a[2]), "r"(a[3]), "r"(b[0]), "r"(b[1]));
}

// ---------------- setup: fold BN into weights, f16 B tiles ------------------
__global__ void setup_kernel(const float* __restrict__ w1, const float* __restrict__ b1,
                             const float* __restrict__ g1, const float* __restrict__ be1,
                             const float* __restrict__ m1, const float* __restrict__ v1,
                             const float* __restrict__ w2, const float* __restrict__ b2,
                             const float* __restrict__ g2, const float* __restrict__ be2,
                             const float* __restrict__ m2, const float* __restrict__ v2) {
    __shared__ float A1s[HID], A2s[TOK];
    int tid = threadIdx.x;
    if (tid < HID) {
        float a = g1[tid] * rsqrtf(v1[tid] + BN_EPS);
        A1s[tid] = a;
        g_c1[tid] = (b1[tid] - m1[tid]) * a + be1[tid];
    }
    if (tid < TOK) {
        float a = g2[tid] * rsqrtf(v2[tid] + BN_EPS);
        A2s[tid] = a;
        g_c2[tid] = (b2[tid] - m2[tid]) * a + be2[tid];
    }
    __syncthreads();
    for (int i = tid; i < TPR * HID; i += blockDim.x) g_w1f[i] = w1[i] * A1s[i % HID];
    for (int i = tid; i < TOK * 16; i += blockDim.x) {
        int n = i >> 4, p = i & 15;
        g_w2h[i] = h2_bits(w2[(2 * p) * TOK + n] * A2s[n],
                           w2[(2 * p + 1) * TOK + n] * A2s[n]);
    }
}

// ---------------- fused TPR MLP (single f16 HMMA) + max + (x+bias) ----------
#define H1_STRIDE 17
extern __shared__ uint32_t sm_u[];
__global__ __launch_bounds__(256)
void fused_tpr_kernel(const float* __restrict__ r, const float* __restrict__ x) {
    uint32_t* smH = sm_u;                       // [512][17] f16 pairs
    __shared__ float W1s[TPR * HID], C1s[HID];
    const int tid = threadIdx.x;
    const int bs = blockIdx.x;

    for (int i = tid; i < TPR * HID; i += 256) W1s[i] = g_w1f[i];
    if (tid < HID) C1s[tid] = g_c1[tid];
    __syncthreads();

    const float* rbase = r + (size_t)bs * TT * TPR;
#pragma unroll
    for (int tt = 0; tt < 2; tt++) {
        int t = tid + tt * 256;
        const float4* rp = reinterpret_cast<const float4*>(rbase + (size_t)t * TPR);
        float4 v0 = rp[0], v1 = rp[1], v2 = rp[2];
        float rv[TPR] = {v0.x, v0.y, v0.z, v0.w, v1.x, v1.y, v1.z, v1.w,
                         v2.x, v2.y, v2.z, v2.w};
        float hv[HID];
#pragma unroll
        for (int h = 0; h < HID; h++) {
            float acc = C1s[h];
#pragma unroll
            for (int d = 0; d < TPR; d++) acc = fmaf(rv[d], W1s[d * HID + h], acc);
            hv[h] = fmaxf(acc, 0.f);
        }
#pragma unroll
        for (int p = 0; p < 16; p++)
            smH[t * H1_STRIDE + p] = h2_bits(hv[2 * p], hv[2 * p + 1]);
    }

    const int wid = tid >> 5, lane = tid & 31;
    const int g = lane >> 2, tig = lane & 3;
    const int nb = wid * 32;
    uint32_t Bh[4][4];
#pragma unroll
    for (int sub = 0; sub < 4; sub++) {
        int n = nb + sub * 8 + g;
#pragma unroll
        for (int s = 0; s < 2; s++) {
            Bh[sub][s * 2 + 0] = g_w2h[n * 16 + tig + 8 * s];
            Bh[sub][s * 2 + 1] = g_w2h[n * 16 + tig + 4 + 8 * s];
        }
    }
    __syncthreads();

    float mx[4][2];
#pragma unroll
    for (int sub = 0; sub < 4; sub++) { mx[sub][0] = -3.4e38f; mx[sub][1] = -3.4e38f; }

    for (int mi = 0; mi < 32; mi++) {
        const int r0 = mi * 16 + g;
        uint32_t Ah[2][4];
#pragma unroll
        for (int s = 0; s < 2; s++) {
            int o0 = r0 * H1_STRIDE + tig + 8 * s;
            int o1 = (r0 + 8) * H1_STRIDE + tig + 8 * s;
            Ah[s][0] = smH[o0];     Ah[s][1] = smH[o1];
            Ah[s][2] = smH[o0 + 4]; Ah[s][3] = smH[o1 + 4];
        }
#pragma unroll
        for (int sub = 0; sub < 4; sub++) {
            float acc[4] = {0.f, 0.f, 0.f, 0.f};
            mmaH(acc, Ah[0], &Bh[sub][0]);
            mmaH(acc, Ah[1], &Bh[sub][2]);
            mx[sub][0] = fmaxf(mx[sub][0], fmaxf(acc[0], acc[2]));
            mx[sub][1] = fmaxf(mx[sub][1], fmaxf(acc[1], acc[3]));
        }
    }
#pragma unroll
    for (int sub = 0; sub < 4; sub++) {
#pragma unroll
        for (int j = 0; j < 2; j++) {
            float v = mx[sub][j];
            v = fmaxf(v, __shfl_xor_sync(0xffffffffu, v, 4));
            v = fmaxf(v, __shfl_xor_sync(0xffffffffu, v, 8));
            v = fmaxf(v, __shfl_xor_sync(0xffffffffu, v, 16));
            if (lane < 4) {
                int c = nb + sub * 8 + 2 * lane + j;
                g_xb[(size_t)bs * TOK + c] =
                    x[(size_t)bs * TOK + c] + fmaxf(v + g_c2[c], 0.f);
            }
        }
    }
}

// ---------------- qkv = xb @ w_qkv  (64x64 tiles, 256 thr, LDS.128) ---------
__global__ void qkv_kernel(const float* __restrict__ w_qkv) {
    __shared__ float As[16][68];
    __shared__ float Bs[16][68];
    const int tid = threadIdx.x;
    const int tx = tid & 15, ty = tid >> 4;
    const int m0 = blockIdx.y * 64, n0 = blockIdx.x * 64;
    float acc[4][4] = {};
    float pa[4], pb[4];
#pragma unroll
    for (int i = 0; i < 4; i++) {
        int idx = tid + i * 256;
        pa[i] = g_xb[(size_t)(m0 + (idx >> 4)) * TOK + (idx & 15)];
        pb[i] = w_qkv[(size_t)(idx >> 6) * 768 + n0 + (idx & 63)];
    }
    for (int k0 = 0; k0 < TOK; k0 += 16) {
#pragma unroll
        for (int i = 0; i < 4; i++) {
            int idx = tid + i * 256;
            As[idx & 15][idx >> 4] = pa[i];
            Bs[idx >> 6][idx & 63] = pb[i];
        }
        __syncthreads();
        if (k0 + 16 < TOK) {
#pragma unroll
            for (int i = 0; i < 4; i++) {
                int idx = tid + i * 256;
                pa[i] = g_xb[(size_t)(m0 + (idx >> 4)) * TOK + k0 + 16 + (idx & 15)];
                pb[i] = w_qkv[(size_t)(k0 + 16 + (idx >> 6)) * 768 + n0 + (idx & 63)];
            }
        }
#pragma unroll
        for (int kk = 0; kk < 16; kk++) {
            float4 a4 = *reinterpret_cast<const float4*>(&As[kk][ty * 4]);
            float4 b4 = *reinterpret_cast<const float4*>(&Bs[kk][tx * 4]);
            float a[4] = {a4.x, a4.y, a4.z, a4.w};
            float b[4] = {b4.x, b4.y, b4.z, b4.w};
#pragma unroll
            for (int i = 0; i < 4; i++)
#pragma unroll
                for (int j = 0; j < 4; j++) acc[i][j] = fmaf(a[i], b[j], acc[i][j]);
        }
        __syncthreads();
    }
#pragma unroll
    for (int i = 0; i < 4; i++)
#pragma unroll
        for (int j = 0; j < 4; j++)
            g_qkv[(size_t)(m0 + ty * 4 + i) * 768 + n0 + tx * 4 + j] = acc[i][j];
}

// ---------------- dots = q @ k^T * scale  (32x64, 128 thr, LDS.128) ---------
__global__ __launch_bounds__(128) void dots_kernel() {
    __shared__ float As[16][36];
    __shared__ float Bs[16][68];
    const int tid = threadIdx.x;
    const int tx = tid & 15, ty = tid >> 4;
    const int b = blockIdx.z;
    const int m0 = blockIdx.x * 32, n0 = blockIdx.y * 64;
    const float* q = g_qkv + (size_t)b * TT * 768;
    const float* k = g_qkv + (size_t)b * TT * 768 + INNER;
    float acc[4][4] = {};
    float pa[4], pb[8];
#pragma unroll
    for (int i = 0; i < 4; i++) {
        int idx = tid + i * 128;
        pa[i] = q[(size_t)(m0 + (idx >> 4)) * 768 + (idx & 15)];
    }
#pragma unroll
    for (int i = 0; i < 8; i++) {
        int idx = tid + i * 128;
        pb[i] = k[(size_t)(n0 + (idx >> 4)) * 768 + (idx & 15)];
    }
    for (int k0 = 0; k0 < INNER; k0 += 16) {
#pragma unroll
        for (int i = 0; i < 4; i++) { int idx = tid + i * 128; As[idx & 15][idx >> 4] = pa[i]; }
#pragma unroll
        for (int i = 0; i < 8; i++) { int idx = tid + i * 128; Bs[idx & 15][idx >> 4] = pb[i]; }
        __syncthreads();
        if (k0 + 16 < INNER) {
#pragma unroll
            for (int i = 0; i < 4; i++) {
                int idx = tid + i * 128;
                pa[i] = q[(size_t)(m0 + (idx >> 4)) * 768 + k0 + 16 + (idx & 15)];
            }
#pragma unroll
            for (int i = 0; i < 8; i++) {
                int idx = tid + i * 128;
                pb[i] = k[(size_t)(n0 + (idx >> 4)) * 768 + k0 + 16 + (idx & 15)];
            }
        }
#pragma unroll
        for (int kk = 0; kk < 16; kk++) {
            float4 a4 = *reinterpret_cast<const float4*>(&As[kk][ty * 4]);
            float4 b4 = *reinterpret_cast<const float4*>(&Bs[kk][tx * 4]);
            float a[4] = {a4.x, a4.y, a4.z, a4.w};
            float bb[4] = {b4.x, b4.y, b4.z, b4.w};
#pragma unroll
            for (int i = 0; i < 4; i++)
#pragma unroll
                for (int j = 0; j < 4; j++) acc[i][j] = fmaf(a[i], bb[j], acc[i][j]);
        }
        __syncthreads();
    }
    float* dst = g_dots + (size_t)b * TT * TT;
#pragma unroll
    for (int i = 0; i < 4; i++)
#pragma unroll
        for (int j = 0; j < 4; j++)
            dst[(size_t)(m0 + ty * 4 + i) * TT + n0 + tx * 4 + j] = acc[i][j] * ATT_SCALE;
}

// ---------------- out = softmax(dots) @ v  (fused, 32x64, 128 thr) ----------
__global__ __launch_bounds__(128) void out_kernel(float* __restrict__ out) {
    __shared__ float As[16][36];
    __shared__ float Bs[16][68];
    __shared__ float rowm[32], rowinv[32];
    const int tid = threadIdx.x;
    const int tx = tid & 15, ty = tid >> 4;
    const int wid = tid >> 5, lane = tid & 31;
    const int b = blockIdx.z;
    const int m0 = blockIdx.y * 32, n0 = blockIdx.x * 64;
    const float* dots = g_dots + (size_t)b * TT * TT;
    const float* v = g_qkv + (size_t)b * TT * 768 + 2 * INNER;

    // Stats prologue: warp w handles rows {w, w+4, ..., w+28}; each lane
    // scans 16 strided cols (coalesced), shuffle-reduces max then sum(exp).
    for (int rr = wid; rr < 32; rr += 4) {
        const float* prow = dots + (size_t)(m0 + rr) * TT;
        float vv[16];
#pragma unroll
        for (int j = 0; j < 16; j++) vv[j] = prow[lane + 32 * j];
        float mx = vv[0];
#pragma unroll
        for (int j = 1; j < 16; j++) mx = fmaxf(mx, vv[j]);
#pragma unroll
        for (int o = 16; o; o >>= 1) mx = fmaxf(mx, __shfl_xor_sync(0xffffffffu, mx, o));
        float s = 0.f;
#pragma unroll
        for (int j = 0; j < 16; j++) s += __expf(vv[j] - mx);
#pragma unroll
        for (int o = 16; o; o >>= 1) s += __shfl_xor_sync(0xffffffffu, s, o);
        if (lane == 0) { rowm[rr] = mx; rowinv[rr] = 1.f / s; }
    }
    __syncthreads();

    // Each thread stages 4 fixed local rows -> cache their stats in registers.
    float rm[4], ri[4];
#pragma unroll
    for (int i = 0; i < 4; i++) {
        int row = (tid + i * 128) >> 4;
        rm[i] = rowm[row];
        ri[i] = rowinv[row];
    }

    float acc[4][4] = {};
    float pa[4], pb[8];
#pragma unroll
    for (int i = 0; i < 4; i++) {
        int idx = tid + i * 128;
        pa[i] = dots[(size_t)(m0 + (idx >> 4)) * TT + (idx & 15)];
    }
#pragma unroll
    for (int i = 0; i < 8; i++) {
        int idx = tid + i * 128;
        pb[i] = v[(size_t)(idx >> 6) * 768 + n0 + (idx & 63)];
    }
    for (int k0 = 0; k0 < TT; k0 += 16) {
#pragma unroll
        for (int i = 0; i < 4; i++) {
            int idx = tid + i * 128;
            As[idx & 15][idx >> 4] = __expf(pa[i] - rm[i]) * ri[i];  // softmax on the fly
        }
#pragma unroll
        for (int i = 0; i < 8; i++) { int idx = tid + i * 128; Bs[idx >> 6][idx & 63] = pb[i]; }
        __syncthreads();
        if (k0 + 16 < TT) {
#pragma unroll
            for (int i = 0; i < 4; i++) {
                int idx = tid + i * 128;
                pa[i] = dots[(size_t)(m0 + (idx >> 4)) * TT + k0 + 16 + (idx & 15)];
            }
#pragma unroll
            for (int i = 0; i < 8; i++) {
                int idx = tid + i * 128;
                pb[i] = v[(size_t)(k0 + 16 + (idx >> 6)) * 768 + n0 + (idx & 63)];
            }
        }
#pragma unroll
        for (int kk = 0; kk < 16; kk++) {
            float4 a4 = *reinterpret_cast<const float4*>(&As[kk][ty * 4]);
            float4 b4 = *reinterpret_cast<const float4*>(&Bs[kk][tx * 4]);
            float a[4] = {a4.x, a4.y, a4.z, a4.w};
            float bb[4] = {b4.x, b4.y, b4.z, b4.w};
#pragma unroll
            for (int i = 0; i < 4; i++)
#pragma unroll
                for (int j = 0; j < 4; j++) acc[i][j] = fmaf(a[i], bb[j], acc[i][j]);
        }
        __syncthreads();
    }
#pragma unroll
    for (int i = 0; i < 4; i++)
#pragma unroll
        for (int j = 0; j < 4; j++)
            out[(size_t)(b * TT + m0 + ty * 4 + i) * INNER + n0 + tx * 4 + j] = acc[i][j];
}

// ---------------- launch ------------------------------------------------------
extern "C" void kernel_launch(void* const* d_in, const int* in_sizes, int n_in,
                              void* d_out, int out_size) {
    const float* x     = (const float*)d_in[0];
    const float* r     = (const float*)d_in[1];
    const float* w1    = (const float*)d_in[2];
    const float* b1    = (const float*)d_in[3];
    const float* g1    = (const float*)d_in[4];
    const float* be1   = (const float*)d_in[5];
    const float* m1    = (const float*)d_in[6];
    const float* v1    = (const float*)d_in[7];
    const float* w2    = (const float*)d_in[8];
    const float* b2    = (const float*)d_in[9];
    const float* g2    = (const float*)d_in[10];
    const float* be2   = (const float*)d_in[11];
    const float* m2    = (const float*)d_in[12];
    const float* v2    = (const float*)d_in[13];
    const float* w_qkv = (const float*)d_in[14];
    float* out = (float*)d_out;

    setup_kernel<<<1, 256>>>(w1, b1, g1, be1, m1, v1, w2, b2, g2, be2, m2, v2);

    int smem_bytes = (TT * H1_STRIDE) * (int)sizeof(uint32_t); // 34816
    cudaFuncSetAttribute(fused_tpr_kernel, cudaFuncAttributeMaxDynamicSharedMemorySize, smem_bytes);
    fused_tpr_kernel<<<BD * TT, 256, smem_bytes>>>(r, x);

    qkv_kernel<<<dim3(768 / 64, 1024 / 64), 256>>>(w_qkv);
    dots_kernel<<<dim3(TT / 32, TT / 64, BD), 128>>>();
    out_kernel<<<dim3(INNER / 64, TT / 32, BD), 128>>>(out);
}

// round 17
// speedup vs baseline: 1.0937x; 1.0937x over previous
#include <cuda_runtime.h>
#include <cuda_fp16.h>
#include <cstdint>

#define TT 512
#define BD 2
#define TOK 256
#define TPR 12
#define HID 32
#define INNER 256
#define ATT_SCALE 0.0625f
#define BN_EPS 1e-5f

// ---------------- scratch (device globals: no allocation allowed) ----------
__device__ float g_w1f[TPR * HID];
__device__ float g_c1[HID];
__device__ float g_c2[TOK];
__device__ uint32_t g_w2h[TOK * 16];     // w2^T, BN-folded, f16 pairs [n][kpair]
__device__ float g_xb[BD * TT * TOK];
__device__ float g_qkv[BD * TT * 3 * INNER];
__device__ float g_dots[BD * TT * TT];

__device__ __forceinline__ uint32_t h2_bits(float a, float b) {
    __half2 h = __floats2half2_rn(a, b);
    return *reinterpret_cast<uint32_t*>(&h);
}

// mma.sync m16n8k16 f16 (baseline PTX, works on sm_103)
__device__ __forceinline__ void mmaH(float* d, const uint32_t* a, const uint32_t* b) {
    asm volatile(
        "mma.sync.aligned.m16n8k16.row.col.f32.f16.f16.f32 "
        "{%0,%1,%2,%3}, {%4,%5,%6,%7}, {%8,%9}, {%0,%1,%2,%3};"
        : "+f"(d[0]), "+f"(d[1]), "+f"(d[2]), "+f"(d[3])
        : "r"(a[0]), "r"(a[1]), "r"(a[2]), "r"(a[3]), "r"(b[0]), "r"(b[1]));
}

// ---------------- setup: fold BN into weights (parallelized) ----------------
__global__ void setup_kernel(const float* __restrict__ w1, const float* __restrict__ b1,
                             const float* __restrict__ g1, const float* __restrict__ be1,
                             const float* __restrict__ m1, const float* __restrict__ v1,
                             const float* __restrict__ w2, const float* __restrict__ b2,
                             const float* __restrict__ g2, const float* __restrict__ be2,
                             const float* __restrict__ m2, const float* __restrict__ v2) {
    __shared__ float A1s[HID], A2s[TOK];
    const int tid = threadIdx.x, blk = blockIdx.x;
    if (tid < TOK) A2s[tid] = g2[tid] * rsqrtf(v2[tid] + BN_EPS);
    if (blk == 0) {
        if (tid < HID) {
            float a = g1[tid] * rsqrtf(v1[tid] + BN_EPS);
            A1s[tid] = a;
            g_c1[tid] = (b1[tid] - m1[tid]) * a + be1[tid];
        }
        if (tid < TOK) g_c2[tid] = (b2[tid] - m2[tid]) * A2s[tid] + be2[tid];
        __syncthreads();
        for (int i = tid; i < TPR * HID; i += 256) g_w1f[i] = w1[i] * A1s[i % HID];
    } else {
        __syncthreads();
        int base = (blk - 1) * 512;           // 8 blocks x 512 = TOK*16
        for (int i = base + tid; i < base + 512; i += 256) {
            int n = i >> 4, p = i & 15;
            g_w2h[i] = h2_bits(w2[(2 * p) * TOK + n] * A2s[n],
                               w2[(2 * p + 1) * TOK + n] * A2s[n]);
        }
    }
}

// ---------------- fused TPR MLP (single f16 HMMA) + max + (x+bias) ----------
#define H1_STRIDE 17
extern __shared__ uint32_t sm_u[];
__global__ __launch_bounds__(256)
void fused_tpr_kernel(const float* __restrict__ r, const float* __restrict__ x) {
    uint32_t* smH = sm_u;                       // [512][17] f16 pairs
    __shared__ float W1s[TPR * HID], C1s[HID];
    const int tid = threadIdx.x;
    const int bs = blockIdx.x;

    for (int i = tid; i < TPR * HID; i += 256) W1s[i] = g_w1f[i];
    if (tid < HID) C1s[tid] = g_c1[tid];
    __syncthreads();

    const float* rbase = r + (size_t)bs * TT * TPR;
#pragma unroll
    for (int tt = 0; tt < 2; tt++) {
        int t = tid + tt * 256;
        const float4* rp = reinterpret_cast<const float4*>(rbase + (size_t)t * TPR);
        float4 v0 = rp[0], v1 = rp[1], v2 = rp[2];
        float rv[TPR] = {v0.x, v0.y, v0.z, v0.w, v1.x, v1.y, v1.z, v1.w,
                         v2.x, v2.y, v2.z, v2.w};
        float hv[HID];
#pragma unroll
        for (int h = 0; h < HID; h++) {
            float acc = C1s[h];
#pragma unroll
            for (int d = 0; d < TPR; d++) acc = fmaf(rv[d], W1s[d * HID + h], acc);
            hv[h] = fmaxf(acc, 0.f);
        }
#pragma unroll
        for (int p = 0; p < 16; p++)
            smH[t * H1_STRIDE + p] = h2_bits(hv[2 * p], hv[2 * p + 1]);
    }

    const int wid = tid >> 5, lane = tid & 31;
    const int g = lane >> 2, tig = lane & 3;
    const int nb = wid * 32;
    uint32_t Bh[4][4];
#pragma unroll
    for (int sub = 0; sub < 4; sub++) {
        int n = nb + sub * 8 + g;
#pragma unroll
        for (int s = 0; s < 2; s++) {
            Bh[sub][s * 2 + 0] = g_w2h[n * 16 + tig + 8 * s];
            Bh[sub][s * 2 + 1] = g_w2h[n * 16 + tig + 4 + 8 * s];
        }
    }
    __syncthreads();

    float mx[4][2];
#pragma unroll
    for (int sub = 0; sub < 4; sub++) { mx[sub][0] = -3.4e38f; mx[sub][1] = -3.4e38f; }

    for (int mi = 0; mi < 32; mi++) {
        const int r0 = mi * 16 + g;
        uint32_t Ah[2][4];
#pragma unroll
        for (int s = 0; s < 2; s++) {
            int o0 = r0 * H1_STRIDE + tig + 8 * s;
            int o1 = (r0 + 8) * H1_STRIDE + tig + 8 * s;
            Ah[s][0] = smH[o0];     Ah[s][1] = smH[o1];
            Ah[s][2] = smH[o0 + 4]; Ah[s][3] = smH[o1 + 4];
        }
#pragma unroll
        for (int sub = 0; sub < 4; sub++) {
            float acc[4] = {0.f, 0.f, 0.f, 0.f};
            mmaH(acc, Ah[0], &Bh[sub][0]);
            mmaH(acc, Ah[1], &Bh[sub][2]);
            mx[sub][0] = fmaxf(mx[sub][0], fmaxf(acc[0], acc[2]));
            mx[sub][1] = fmaxf(mx[sub][1], fmaxf(acc[1], acc[3]));
        }
    }
#pragma unroll
    for (int sub = 0; sub < 4; sub++) {
#pragma unroll
        for (int j = 0; j < 2; j++) {
            float v = mx[sub][j];
            v = fmaxf(v, __shfl_xor_sync(0xffffffffu, v, 4));
            v = fmaxf(v, __shfl_xor_sync(0xffffffffu, v, 8));
            v = fmaxf(v, __shfl_xor_sync(0xffffffffu, v, 16));
            if (lane < 4) {
                int c = nb + sub * 8 + 2 * lane + j;
                g_xb[(size_t)bs * TOK + c] =
                    x[(size_t)bs * TOK + c] + fmaxf(v + g_c2[c], 0.f);
            }
        }
    }
}

// ---------------- qkv = xb @ w_qkv  (64x64, 256 thr, dbl-buffered smem) -----
__global__ void qkv_kernel(const float* __restrict__ w_qkv) {
    __shared__ float As[2][16][68];
    __shared__ float Bs[2][16][68];
    const int tid = threadIdx.x;
    const int tx = tid & 15, ty = tid >> 4;
    const int m0 = blockIdx.y * 64, n0 = blockIdx.x * 64;
    float acc[4][4] = {};
    float pa[4], pb[4];
    // prologue: tile0 -> smem[0]; tile1 -> regs
#pragma unroll
    for (int i = 0; i < 4; i++) {
        int idx = tid + i * 256;
        As[0][idx & 15][idx >> 4] = g_xb[(size_t)(m0 + (idx >> 4)) * TOK + (idx & 15)];
        Bs[0][idx >> 6][idx & 63] = w_qkv[(size_t)(idx >> 6) * 768 + n0 + (idx & 63)];
    }
#pragma unroll
    for (int i = 0; i < 4; i++) {
        int idx = tid + i * 256;
        pa[i] = g_xb[(size_t)(m0 + (idx >> 4)) * TOK + 16 + (idx & 15)];
        pb[i] = w_qkv[(size_t)(16 + (idx >> 6)) * 768 + n0 + (idx & 63)];
    }
    __syncthreads();
    const int NIT = TOK / 16;   // 16
    for (int it = 0; it < NIT; it++) {
        int cur = it & 1;
        if (it + 1 < NIT) {
#pragma unroll
            for (int i = 0; i < 4; i++) {
                int idx = tid + i * 256;
                As[cur ^ 1][idx & 15][idx >> 4] = pa[i];
                Bs[cur ^ 1][idx >> 6][idx & 63] = pb[i];
            }
        }
        if (it + 2 < NIT) {
            int k0 = (it + 2) * 16;
#pragma unroll
            for (int i = 0; i < 4; i++) {
                int idx = tid + i * 256;
                pa[i] = g_xb[(size_t)(m0 + (idx >> 4)) * TOK + k0 + (idx & 15)];
                pb[i] = w_qkv[(size_t)(k0 + (idx >> 6)) * 768 + n0 + (idx & 63)];
            }
        }
#pragma unroll
        for (int kk = 0; kk < 16; kk++) {
            float4 a4 = *reinterpret_cast<const float4*>(&As[cur][kk][ty * 4]);
            float4 b4 = *reinterpret_cast<const float4*>(&Bs[cur][kk][tx * 4]);
            float a[4] = {a4.x, a4.y, a4.z, a4.w};
            float b[4] = {b4.x, b4.y, b4.z, b4.w};
#pragma unroll
            for (int i = 0; i < 4; i++)
#pragma unroll
                for (int j = 0; j < 4; j++) acc[i][j] = fmaf(a[i], b[j], acc[i][j]);
        }
        __syncthreads();
    }
#pragma unroll
    for (int i = 0; i < 4; i++)
#pragma unroll
        for (int j = 0; j < 4; j++)
            g_qkv[(size_t)(m0 + ty * 4 + i) * 768 + n0 + tx * 4 + j] = acc[i][j];
}

// ---------------- dots = q @ k^T * scale  (32x64, 128 thr, dbl-buffered) ----
__global__ __launch_bounds__(128) void dots_kernel() {
    __shared__ float As[2][16][36];
    __shared__ float Bs[2][16][68];
    const int tid = threadIdx.x;
    const int tx = tid & 15, ty = tid >> 4;
    const int b = blockIdx.z;
    const int m0 = blockIdx.x * 32, n0 = blockIdx.y * 64;
    const float* q = g_qkv + (size_t)b * TT * 768;
    const float* k = g_qkv + (size_t)b * TT * 768 + INNER;
    float acc[4][4] = {};
    float pa[4], pb[8];
#pragma unroll
    for (int i = 0; i < 4; i++) {
        int idx = tid + i * 128;
        As[0][idx & 15][idx >> 4] = q[(size_t)(m0 + (idx >> 4)) * 768 + (idx & 15)];
    }
#pragma unroll
    for (int i = 0; i < 8; i++) {
        int idx = tid + i * 128;
        Bs[0][idx & 15][idx >> 4] = k[(size_t)(n0 + (idx >> 4)) * 768 + (idx & 15)];
    }
#pragma unroll
    for (int i = 0; i < 4; i++) {
        int idx = tid + i * 128;
        pa[i] = q[(size_t)(m0 + (idx >> 4)) * 768 + 16 + (idx & 15)];
    }
#pragma unroll
    for (int i = 0; i < 8; i++) {
        int idx = tid + i * 128;
        pb[i] = k[(size_t)(n0 + (idx >> 4)) * 768 + 16 + (idx & 15)];
    }
    __syncthreads();
    const int NIT = INNER / 16;   // 16
    for (int it = 0; it < NIT; it++) {
        int cur = it & 1;
        if (it + 1 < NIT) {
#pragma unroll
            for (int i = 0; i < 4; i++) { int idx = tid + i * 128; As[cur ^ 1][idx & 15][idx >> 4] = pa[i]; }
#pragma unroll
            for (int i = 0; i < 8; i++) { int idx = tid + i * 128; Bs[cur ^ 1][idx & 15][idx >> 4] = pb[i]; }
        }
        if (it + 2 < NIT) {
            int k0 = (it + 2) * 16;
#pragma unroll
            for (int i = 0; i < 4; i++) {
                int idx = tid + i * 128;
                pa[i] = q[(size_t)(m0 + (idx >> 4)) * 768 + k0 + (idx & 15)];
            }
#pragma unroll
            for (int i = 0; i < 8; i++) {
                int idx = tid + i * 128;
                pb[i] = k[(size_t)(n0 + (idx >> 4)) * 768 + k0 + (idx & 15)];
            }
        }
#pragma unroll
        for (int kk = 0; kk < 16; kk++) {
            float4 a4 = *reinterpret_cast<const float4*>(&As[cur][kk][ty * 4]);
            float4 b4 = *reinterpret_cast<const float4*>(&Bs[cur][kk][tx * 4]);
            float a[4] = {a4.x, a4.y, a4.z, a4.w};
            float bb[4] = {b4.x, b4.y, b4.z, b4.w};
#pragma unroll
            for (int i = 0; i < 4; i++)
#pragma unroll
                for (int j = 0; j < 4; j++) acc[i][j] = fmaf(a[i], bb[j], acc[i][j]);
        }
        __syncthreads();
    }
    float* dst = g_dots + (size_t)b * TT * TT;
#pragma unroll
    for (int i = 0; i < 4; i++)
#pragma unroll
        for (int j = 0; j < 4; j++)
            dst[(size_t)(m0 + ty * 4 + i) * TT + n0 + tx * 4 + j] = acc[i][j] * ATT_SCALE;
}

// ---------------- row softmax over 512 --------------------------------------
__global__ void softmax_kernel() {
    const int row = blockIdx.x;
    float* p = g_dots + (size_t)row * TT;
    const int tid = threadIdx.x;
    const int w = tid >> 5, l = tid & 31;
    float v[4];
#pragma unroll
    for (int i = 0; i < 4; i++) v[i] = p[tid + i * 128];
    float m = fmaxf(fmaxf(v[0], v[1]), fmaxf(v[2], v[3]));
#pragma unroll
    for (int o = 16; o; o >>= 1) m = fmaxf(m, __shfl_xor_sync(0xffffffffu, m, o));
    __shared__ float red[4], red2[4];
    if (!l) red[w] = m;
    __syncthreads();
    m = fmaxf(fmaxf(red[0], red[1]), fmaxf(red[2], red[3]));
    float s = 0.f;
#pragma unroll
    for (int i = 0; i < 4; i++) { v[i] = __expf(v[i] - m); s += v[i]; }
#pragma unroll
    for (int o = 16; o; o >>= 1) s += __shfl_xor_sync(0xffffffffu, s, o);
    if (!l) red2[w] = s;
    __syncthreads();
    s = red2[0] + red2[1] + red2[2] + red2[3];
    float inv = 1.f / s;
#pragma unroll
    for (int i = 0; i < 4; i++) p[tid + i * 128] = v[i] * inv;
}

// ---------------- out = attn @ v  (32x64, 128 thr, dbl-buffered) ------------
__global__ __launch_bounds__(128) void out_kernel(float* __restrict__ out) {
    __shared__ float As[2][16][36];
    __shared__ float Bs[2][16][68];
    const int tid = threadIdx.x;
    const int tx = tid & 15, ty = tid >> 4;
    const int b = blockIdx.z;
    const int m0 = blockIdx.y * 32, n0 = blockIdx.x * 64;
    const float* attn = g_dots + (size_t)b * TT * TT;
    const float* v = g_qkv + (size_t)b * TT * 768 + 2 * INNER;
    float acc[4][4] = {};
    float pa[4], pb[8];
#pragma unroll
    for (int i = 0; i < 4; i++) {
        int idx = tid + i * 128;
        As[0][idx & 15][idx >> 4] = attn[(size_t)(m0 + (idx >> 4)) * TT + (idx & 15)];
    }
#pragma unroll
    for (int i = 0; i < 8; i++) {
        int idx = tid + i * 128;
        Bs[0][idx >> 6][idx & 63] = v[(size_t)(idx >> 6) * 768 + n0 + (idx & 63)];
    }
#pragma unroll
    for (int i = 0; i < 4; i++) {
        int idx = tid + i * 128;
        pa[i] = attn[(size_t)(m0 + (idx >> 4)) * TT + 16 + (idx & 15)];
    }
#pragma unroll
    for (int i = 0; i < 8; i++) {
        int idx = tid + i * 128;
        pb[i] = v[(size_t)(16 + (idx >> 6)) * 768 + n0 + (idx & 63)];
    }
    __syncthreads();
    const int NIT = TT / 16;   // 32
    for (int it = 0; it < NIT; it++) {
        int cur = it & 1;
        if (it + 1 < NIT) {
#pragma unroll
            for (int i = 0; i < 4; i++) { int idx = tid + i * 128; As[cur ^ 1][idx & 15][idx >> 4] = pa[i]; }
#pragma unroll
            for (int i = 0; i < 8; i++) { int idx = tid + i * 128; Bs[cur ^ 1][idx >> 6][idx & 63] = pb[i]; }
        }
        if (it + 2 < NIT) {
            int k0 = (it + 2) * 16;
#pragma unroll
            for (int i = 0; i < 4; i++) {
                int idx = tid + i * 128;
                pa[i] = attn[(size_t)(m0 + (idx >> 4)) * TT + k0 + (idx & 15)];
            }
#pragma unroll
            for (int i = 0; i < 8; i++) {
                int idx = tid + i * 128;
                pb[i] = v[(size_t)(k0 + (idx >> 6)) * 768 + n0 + (idx & 63)];
            }
        }
#pragma unroll
        for (int kk = 0; kk < 16; kk++) {
            float4 a4 = *reinterpret_cast<const float4*>(&As[cur][kk][ty * 4]);
            float4 b4 = *reinterpret_cast<const float4*>(&Bs[cur][kk][tx * 4]);
            float a[4] = {a4.x, a4.y, a4.z, a4.w};
            float bb[4] = {b4.x, b4.y, b4.z, b4.w};
#pragma unroll
            for (int i = 0; i < 4; i++)
#pragma unroll
                for (int j = 0; j < 4; j++) acc[i][j] = fmaf(a[i], bb[j], acc[i][j]);
        }
        __syncthreads();
    }
#pragma unroll
    for (int i = 0; i < 4; i++)
#pragma unroll
        for (int j = 0; j < 4; j++)
            out[(size_t)(b * TT + m0 + ty * 4 + i) * INNER + n0 + tx * 4 + j] = acc[i][j];
}

// ---------------- launch ------------------------------------------------------
extern "C" void kernel_launch(void* const* d_in, const int* in_sizes, int n_in,
                              void* d_out, int out_size) {
    const float* x     = (const float*)d_in[0];
    const float* r     = (const float*)d_in[1];
    const float* w1    = (const float*)d_in[2];
    const float* b1    = (const float*)d_in[3];
    const float* g1    = (const float*)d_in[4];
    const float* be1   = (const float*)d_in[5];
    const float* m1    = (const float*)d_in[6];
    const float* v1    = (const float*)d_in[7];
    const float* w2    = (const float*)d_in[8];
    const float* b2    = (const float*)d_in[9];
    const float* g2    = (const float*)d_in[10];
    const float* be2   = (const float*)d_in[11];
    const float* m2    = (const float*)d_in[12];
    const float* v2    = (const float*)d_in[13];
    const float* w_qkv = (const float*)d_in[14];
    float* out = (float*)d_out;

    setup_kernel<<<9, 256>>>(w1, b1, g1, be1, m1, v1, w2, b2, g2, be2, m2, v2);

    int smem_bytes = (TT * H1_STRIDE) * (int)sizeof(uint32_t); // 34816
    cudaFuncSetAttribute(fused_tpr_kernel, cudaFuncAttributeMaxDynamicSharedMemorySize, smem_bytes);
    fused_tpr_kernel<<<BD * TT, 256, smem_bytes>>>(r, x);

    qkv_kernel<<<dim3(768 / 64, 1024 / 64), 256>>>(w_qkv);
    dots_kernel<<<dim3(TT / 32, TT / 64, BD), 128>>>();
    softmax_kernel<<<BD * TT, 128>>>();
    out_kernel<<<dim3(INNER / 64, TT / 32, BD), 128>>>(out);
}